// round 2
// baseline (speedup 1.0000x reference)
#include <cuda_runtime.h>
#include <math.h>

#define SEQ   512
#define BATCH 2048
#define HID   512
#define INX   31      // x feature dim (IN - OUT)
#define KC    1024    // combined K = [x0 | h]
#define G4    2048    // 4*H gate outputs
#define NBLK  148
#define NTHR  256
#define NWARP 8

// ---------------- persistent state (device globals; no allocs) ----------------
__device__ float g_xh[BATCH * KC];        // [b][k]: k<512 -> x0, k>=512 -> h
__device__ float g_c [BATCH * HID];       // cell state
__device__ float g_gates[BATCH * G4];     // gate pre-activations (biased)
__device__ float g_WcT[KC * G4];          // [k][n] = concat(W_ih, W_hh) transposed
__device__ float g_WiT[32 * HID];         // [k][j] = W_in transposed
__device__ unsigned g_bar_count;
__device__ volatile unsigned g_bar_gen;

// ---------------- grid-wide barrier (all 148 CTAs resident) -------------------
__device__ __forceinline__ void grid_sync() {
    __syncthreads();
    if (threadIdx.x == 0) {
        unsigned gen = g_bar_gen;
        __threadfence();
        if (atomicAdd(&g_bar_count, 1u) == (unsigned)(NBLK - 1)) {
            g_bar_count = 0;
            __threadfence();
            g_bar_gen = gen + 1;
        } else {
            while (g_bar_gen == gen) { __nanosleep(64); }
        }
        __threadfence();
    }
    __syncthreads();
}

__device__ __forceinline__ float sigf(float v) { return 1.0f / (1.0f + expf(-v)); }

__device__ __forceinline__ unsigned long long pack2(float lo, float hi) {
    unsigned long long r;
    asm("mov.b64 %0, {%1, %2};" : "=l"(r) : "f"(lo), "f"(hi));
    return r;
}

__global__ __launch_bounds__(NTHR, 1) void lstm_persist(
    const float* __restrict__ x,   const float* __restrict__ h0,
    const float* __restrict__ c0,  const float* __restrict__ y0,
    const float* __restrict__ W_in,  const float* __restrict__ b_in,
    const float* __restrict__ W_ih,  const float* __restrict__ W_hh,
    const float* __restrict__ b_ih,  const float* __restrict__ b_hh,
    const float* __restrict__ W_out, const float* __restrict__ b_out,
    float* __restrict__ out)
{
    __shared__ float binS [HID];
    __shared__ float woutS[HID];
    __shared__ float inpS [NWARP * 32];
    __shared__ float As   [16 * 132];   // padded: (k 16) x (m 128 +4)
    __shared__ float Bs   [16 * 128];   // (k 16) x (n 128)

    const int tid  = threadIdx.x;
    const int bid  = blockIdx.x;
    const int warp = tid >> 5, lane = tid & 31;

    // ---- per-CTA small staging ----
    for (int i = tid; i < HID; i += NTHR) { binS[i] = b_in[i]; woutS[i] = W_out[i]; }

    // ---- one-time striped init of transposed weights (visible after 1st sync)
    for (int idx = bid * NTHR + tid; idx < KC * G4; idx += NBLK * NTHR) {
        int k = idx >> 11, n = idx & (G4 - 1);
        g_WcT[idx] = (k < HID) ? W_ih[n * HID + k] : W_hh[n * HID + (k - HID)];
    }
    for (int idx = bid * NTHR + tid; idx < 32 * HID; idx += NBLK * NTHR) {
        int j = idx >> 5, k = idx & 31;
        g_WiT[k * HID + j] = W_in[j * 32 + k];
    }
    grid_sync();   // WcT / WiT visible to everyone; L1 first-touch happens after

    const int b0 = (bid * BATCH) / NBLK;
    const int b1 = ((bid + 1) * BATCH) / NBLK;
    const float bout0 = b_out[0];

    // GEMM thread mapping (16n x 16m thread grid, 8x8 micro-tile)
    const int tn  = tid & 15, tm = tid >> 4;
    const int ar  = tid >> 2, aq  = tid & 3;       // A-slab loader: row, k-quad
    const int bk  = tid >> 4, bn4 = (tid & 15) * 4;// B-slab loader: k-row, n-quad

    for (int t = 0; t <= SEQ; ++t) {
        // ================= ROW PHASE (one warp per batch row) ==================
        for (int b = b0 + warp; b < b1; b += NWARP) {
            float ycur;
            if (t == 0) {
                const float4* h04 = (const float4*)h0;
                const float4* c04 = (const float4*)c0;
                float4* xh4 = (float4*)g_xh;
                float4* c4  = (float4*)g_c;
                for (int jj = lane; jj < HID / 4; jj += 32) {
                    xh4[(size_t)b * (KC / 4) + HID / 4 + jj] = h04[(size_t)b * (HID / 4) + jj];
                    c4 [(size_t)b * (HID / 4) + jj]          = c04[(size_t)b * (HID / 4) + jj];
                }
                ycur = y0[b];
            } else {
                float ysum = 0.f;
                #pragma unroll
                for (int ii = 0; ii < 4; ++ii) {
                    const int j4 = lane * 4 + ii * 128;
                    const float* gp = g_gates + (size_t)b * G4 + j4;
                    // gates were written by other SMs -> bypass (stale) L1
                    float4 gi = __ldcg((const float4*)(gp));
                    float4 gf = __ldcg((const float4*)(gp + 512));
                    float4 gg = __ldcg((const float4*)(gp + 1024));
                    float4 go = __ldcg((const float4*)(gp + 1536));
                    float4 cv = *(const float4*)(g_c + (size_t)b * HID + j4);
                    float4 cn, hn;
                    cn.x = sigf(gf.x) * cv.x + sigf(gi.x) * tanhf(gg.x);
                    cn.y = sigf(gf.y) * cv.y + sigf(gi.y) * tanhf(gg.y);
                    cn.z = sigf(gf.z) * cv.z + sigf(gi.z) * tanhf(gg.z);
                    cn.w = sigf(gf.w) * cv.w + sigf(gi.w) * tanhf(gg.w);
                    hn.x = sigf(go.x) * tanhf(cn.x);
                    hn.y = sigf(go.y) * tanhf(cn.y);
                    hn.z = sigf(go.z) * tanhf(cn.z);
                    hn.w = sigf(go.w) * tanhf(cn.w);
                    *(float4*)(g_c  + (size_t)b * HID + j4)       = cn;
                    *(float4*)(g_xh + (size_t)b * KC + HID + j4)  = hn;
                    const float4 wv = *(const float4*)(woutS + j4);
                    ysum += hn.x * wv.x + hn.y * wv.y + hn.z * wv.z + hn.w * wv.w;
                }
                #pragma unroll
                for (int off = 16; off > 0; off >>= 1)
                    ysum += __shfl_down_sync(0xffffffffu, ysum, off);
                ysum = __shfl_sync(0xffffffffu, ysum, 0);
                ycur = ysum + bout0;
                if (lane == 0) out[(size_t)(t - 1) * BATCH + b] = ycur;
            }
            if (t < SEQ) {
                // stage inp = [x_t[b], y] (per-warp shared scratch)
                if (lane < INX) inpS[warp * 32 + lane] = x[((size_t)t * BATCH + b) * INX + lane];
                if (lane == 31) inpS[warp * 32 + 31] = ycur;
                __syncwarp();
                // x0[b][:] = relu(inp @ W_in^T + b_in)
                #pragma unroll
                for (int ii = 0; ii < 4; ++ii) {
                    const int j4 = lane * 4 + ii * 128;
                    float4 acc = *(const float4*)(binS + j4);
                    #pragma unroll
                    for (int k = 0; k < 32; ++k) {
                        const float a = inpS[warp * 32 + k];
                        const float4 w = *(const float4*)(g_WiT + k * HID + j4);
                        acc.x += a * w.x; acc.y += a * w.y;
                        acc.z += a * w.z; acc.w += a * w.w;
                    }
                    acc.x = fmaxf(acc.x, 0.f); acc.y = fmaxf(acc.y, 0.f);
                    acc.z = fmaxf(acc.z, 0.f); acc.w = fmaxf(acc.w, 0.f);
                    *(float4*)(g_xh + (size_t)b * KC + j4) = acc;
                }
                __syncwarp();
            }
        }
        if (t == SEQ) break;

        grid_sync();   // xh complete -> GEMM may read

        // ================= GEMM: gates = xh @ WcT + (b_ih + b_hh) ==============
        for (int tile = bid; tile < 256; tile += NBLK) {
            const int m0 = (tile & 15) * 128;
            const int n0 = (tile >> 4) * 128;
            const int nb = n0 + tn * 8;

            unsigned long long acc[8][4];
            {
                float bias[8];
                #pragma unroll
                for (int u = 0; u < 8; ++u) bias[u] = b_ih[nb + u] + b_hh[nb + u];
                #pragma unroll
                for (int j2 = 0; j2 < 4; ++j2) {
                    unsigned long long bv = pack2(bias[2 * j2], bias[2 * j2 + 1]);
                    #pragma unroll
                    for (int i = 0; i < 8; ++i) acc[i][j2] = bv;
                }
            }

            float4 aR0, aR1, bR0, bR1;
            aR0 = __ldcg((const float4*)(g_xh + (size_t)(m0 + ar     ) * KC + aq * 4));
            aR1 = __ldcg((const float4*)(g_xh + (size_t)(m0 + ar + 64) * KC + aq * 4));
            bR0 = *(const float4*)(g_WcT + (size_t)bk * G4 + n0 + bn4);        // read-only: L1 OK
            bR1 = *(const float4*)(g_WcT + (size_t)bk * G4 + n0 + bn4 + 64);

            for (int kb = 0; kb < KC / 16; ++kb) {
                __syncthreads();
                As[(aq * 4 + 0) * 132 + ar]      = aR0.x;
                As[(aq * 4 + 1) * 132 + ar]      = aR0.y;
                As[(aq * 4 + 2) * 132 + ar]      = aR0.z;
                As[(aq * 4 + 3) * 132 + ar]      = aR0.w;
                As[(aq * 4 + 0) * 132 + ar + 64] = aR1.x;
                As[(aq * 4 + 1) * 132 + ar + 64] = aR1.y;
                As[(aq * 4 + 2) * 132 + ar + 64] = aR1.z;
                As[(aq * 4 + 3) * 132 + ar + 64] = aR1.w;
                *(float4*)(Bs + bk * 128 + bn4)      = bR0;
                *(float4*)(Bs + bk * 128 + bn4 + 64) = bR1;
                __syncthreads();
                if (kb + 1 < KC / 16) {   // prefetch next slab during compute
                    const int k0 = (kb + 1) * 16;
                    aR0 = __ldcg((const float4*)(g_xh + (size_t)(m0 + ar     ) * KC + k0 + aq * 4));
                    aR1 = __ldcg((const float4*)(g_xh + (size_t)(m0 + ar + 64) * KC + k0 + aq * 4));
                    bR0 = *(const float4*)(g_WcT + (size_t)(k0 + bk) * G4 + n0 + bn4);
                    bR1 = *(const float4*)(g_WcT + (size_t)(k0 + bk) * G4 + n0 + bn4 + 64);
                }
                #pragma unroll
                for (int kk = 0; kk < 16; ++kk) {
                    const float4 a0 = *(const float4*)(As + kk * 132 + tm * 8);
                    const float4 a1 = *(const float4*)(As + kk * 132 + tm * 8 + 4);
                    const ulonglong2 q0 = *(const ulonglong2*)(Bs + kk * 128 + tn * 8);
                    const ulonglong2 q1 = *(const ulonglong2*)(Bs + kk * 128 + tn * 8 + 4);
                    const float av[8] = {a0.x, a0.y, a0.z, a0.w, a1.x, a1.y, a1.z, a1.w};
                    #pragma unroll
                    for (int i = 0; i < 8; ++i) {
                        unsigned long long ad;
                        asm("mov.b64 %0, {%1, %1};" : "=l"(ad) : "f"(av[i]));
                        asm("fma.rn.f32x2 %0, %1, %2, %0;" : "+l"(acc[i][0]) : "l"(ad), "l"(q0.x));
                        asm("fma.rn.f32x2 %0, %1, %2, %0;" : "+l"(acc[i][1]) : "l"(ad), "l"(q0.y));
                        asm("fma.rn.f32x2 %0, %1, %2, %0;" : "+l"(acc[i][2]) : "l"(ad), "l"(q1.x));
                        asm("fma.rn.f32x2 %0, %1, %2, %0;" : "+l"(acc[i][3]) : "l"(ad), "l"(q1.y));
                    }
                }
            }

            // epilogue: store 8x8 tile
            #pragma unroll
            for (int i = 0; i < 8; ++i) {
                const int m = m0 + tm * 8 + i;
                float4 o0, o1;
                asm("mov.b64 {%0, %1}, %2;" : "=f"(o0.x), "=f"(o0.y) : "l"(acc[i][0]));
                asm("mov.b64 {%0, %1}, %2;" : "=f"(o0.z), "=f"(o0.w) : "l"(acc[i][1]));
                asm("mov.b64 {%0, %1}, %2;" : "=f"(o1.x), "=f"(o1.y) : "l"(acc[i][2]));
                asm("mov.b64 {%0, %1}, %2;" : "=f"(o1.z), "=f"(o1.w) : "l"(acc[i][3]));
                *(float4*)(g_gates + (size_t)m * G4 + nb)     = o0;
                *(float4*)(g_gates + (size_t)m * G4 + nb + 4) = o1;
            }
        }

        grid_sync();   // gates complete -> next row phase may read
    }
}

extern "C" void kernel_launch(void* const* d_in, const int* in_sizes, int n_in,
                              void* d_out, int out_size) {
    (void)in_sizes; (void)n_in; (void)out_size;
    const float* x     = (const float*)d_in[0];
    const float* h0    = (const float*)d_in[1];
    const float* c0    = (const float*)d_in[2];
    const float* y0    = (const float*)d_in[3];
    const float* W_in  = (const float*)d_in[4];
    const float* b_in  = (const float*)d_in[5];
    const float* W_ih  = (const float*)d_in[6];
    const float* W_hh  = (const float*)d_in[7];
    const float* b_ih  = (const float*)d_in[8];
    const float* b_hh  = (const float*)d_in[9];
    const float* W_out = (const float*)d_in[10];
    const float* b_out = (const float*)d_in[11];
    float* out = (float*)d_out;

    lstm_persist<<<NBLK, NTHR>>>(x, h0, c0, y0, W_in, b_in, W_ih, W_hh,
                                 b_ih, b_hh, W_out, b_out, out);
}

// round 6
// speedup vs baseline: 2.9535x; 2.9535x over previous
#include <cuda_runtime.h>
#include <cuda_bf16.h>
#include <math.h>
#include <stdint.h>

#define SEQ   512
#define BATCH 2048
#define HID   512
#define KC    1024
#define NBLK  148
#define NTHR  256
#define TILES 128           // 16 m-tiles x 8 h-tiles
#define STAGE 98304
#define OFF_AHI 0
#define OFF_ALO 16384
#define OFF_BHI 32768
#define OFF_BLO 65536
#define DYNSMEM (2*STAGE + 1024)
#define GSTR  264           // gates smem row stride (floats)

// ---------------- persistent device state (no allocs) ----------------
__device__ __align__(16) __nv_bfloat16 g_A_hi[BATCH * KC];   // [b][k] k<512:x0, k>=512:h
__device__ __align__(16) __nv_bfloat16 g_A_lo[BATCH * KC];
__device__ __align__(16) __nv_bfloat16 g_B_hi[8 * 256 * KC]; // [hb][n'][k], n'=gate*64+j
__device__ __align__(16) __nv_bfloat16 g_B_lo[8 * 256 * KC];
__device__ float g_bias[8 * 256];
__device__ float g_c[BATCH * HID];
__device__ float g_WiT[32 * HID];
__device__ unsigned g_bar_count;
__device__ volatile unsigned g_bar_gen;

// ---------------- helpers ----------------
__device__ __forceinline__ uint32_t smaddr(const void* p) {
    return (uint32_t)__cvta_generic_to_shared(p);
}
__device__ __forceinline__ void cpasync16(uint32_t dst, const void* src) {
    asm volatile("cp.async.cg.shared.global [%0], [%1], 16;" :: "r"(dst), "l"(src));
}
__device__ __forceinline__ void cp_commit() {
    asm volatile("cp.async.commit_group;" ::: "memory");
}
__device__ __forceinline__ void cp_wait1() {
    asm volatile("cp.async.wait_group 1;" ::: "memory");
}
__device__ __forceinline__ void cp_wait0() {
    asm volatile("cp.async.wait_group 0;" ::: "memory");
}
__device__ __forceinline__ void ldmx4(uint32_t* r, uint32_t addr) {
    asm volatile("ldmatrix.sync.aligned.m8n8.x4.shared.b16 {%0,%1,%2,%3}, [%4];"
                 : "=r"(r[0]), "=r"(r[1]), "=r"(r[2]), "=r"(r[3]) : "r"(addr));
}
__device__ __forceinline__ void mma16816(float* d, const uint32_t* a, const uint32_t* b) {
    asm volatile("mma.sync.aligned.m16n8k16.row.col.f32.bf16.bf16.f32 "
                 "{%0,%1,%2,%3}, {%4,%5,%6,%7}, {%8,%9}, {%0,%1,%2,%3};"
                 : "+f"(d[0]), "+f"(d[1]), "+f"(d[2]), "+f"(d[3])
                 : "r"(a[0]), "r"(a[1]), "r"(a[2]), "r"(a[3]), "r"(b[0]), "r"(b[1]));
}

__device__ __forceinline__ void grid_sync() {
    __syncthreads();
    if (threadIdx.x == 0) {
        unsigned gen = g_bar_gen;
        __threadfence();
        if (atomicAdd(&g_bar_count, 1u) == (unsigned)(NBLK - 1)) {
            g_bar_count = 0;
            __threadfence();
            g_bar_gen = gen + 1;
        } else {
            while (g_bar_gen == gen) { __nanosleep(64); }
        }
        __threadfence();
    }
    __syncthreads();
}

__device__ __forceinline__ float sigf(float v) {
    return __fdividef(1.0f, 1.0f + __expf(-v));
}
__device__ __forceinline__ float tanh_(float v) {
    return 2.0f * sigf(2.0f * v) - 1.0f;
}

// issue one k-slab (64 k) of A(hi/lo) + B(hi/lo) via cp.async into stage buffer
__device__ __forceinline__ void issue_slab(uint32_t dstbase, int kb, int m0, int hb, int tid) {
    #pragma unroll
    for (int i = 0; i < 4; ++i) {
        int c = tid + i * 256;
        int row = c >> 3, kq = c & 7;
        size_t so = ((size_t)(m0 + row) * KC + (size_t)kb * 64 + kq * 8) * 2;
        unsigned off = (unsigned)(row * 128) + (unsigned)((kq ^ (row & 7)) << 4);
        cpasync16(dstbase + OFF_AHI + off, (const char*)g_A_hi + so);
        cpasync16(dstbase + OFF_ALO + off, (const char*)g_A_lo + so);
    }
    #pragma unroll
    for (int i = 0; i < 8; ++i) {
        int c = tid + i * 256;
        int n = c >> 3, kq = c & 7;
        size_t so = (((size_t)hb * 256 + n) * KC + (size_t)kb * 64 + kq * 8) * 2;
        unsigned off = (unsigned)(n * 128) + (unsigned)((kq ^ (n & 7)) << 4);
        cpasync16(dstbase + OFF_BHI + off, (const char*)g_B_hi + so);
        cpasync16(dstbase + OFF_BLO + off, (const char*)g_B_lo + so);
    }
}

__global__ __launch_bounds__(NTHR, 1) void lstm_persist(
    const float* __restrict__ x,   const float* __restrict__ h0,
    const float* __restrict__ c0,  const float* __restrict__ y0,
    const float* __restrict__ W_in,  const float* __restrict__ b_in,
    const float* __restrict__ W_ih,  const float* __restrict__ W_hh,
    const float* __restrict__ b_ih,  const float* __restrict__ b_hh,
    const float* __restrict__ W_out, const float* __restrict__ b_out,
    float* __restrict__ out)
{
    extern __shared__ char dsm[];
    __shared__ float binS [HID];
    __shared__ float woutS[HID];
    __shared__ float biasS[256];
    __shared__ float inpS [NTHR];

    const int tid  = threadIdx.x;
    const int bid  = blockIdx.x;
    const int warp = tid >> 5, lane = tid & 31;

    // align dynamic smem to 1KB
    uint32_t raw = smaddr(dsm);
    uint32_t sb  = (raw + 1023u) & ~1023u;
    char* base   = dsm + (sb - raw);

    // ---- small per-CTA staging ----
    for (int i = tid; i < HID; i += NTHR) { binS[i] = b_in[i]; woutS[i] = W_out[i]; }

    // ---- one-time global init (striped across grid) ----
    for (int idx = bid * NTHR + tid; idx < 32 * HID; idx += NBLK * NTHR) {
        int j = idx >> 5, k = idx & 31;
        g_WiT[k * HID + j] = W_in[j * 32 + k];
    }
    for (int idx = bid * NTHR + tid; idx < 8 * 256 * KC; idx += NBLK * NTHR) {
        int hb = idx >> 18, rem = idx & 0x3FFFF;
        int n = rem >> 10, k = rem & 1023;
        int gate = n >> 6, j = n & 63;
        int srow = gate * 512 + hb * 64 + j;
        float w = (k < 512) ? W_ih[srow * 512 + k] : W_hh[srow * 512 + (k - 512)];
        __nv_bfloat16 hi = __float2bfloat16(w);
        g_B_hi[idx] = hi;
        g_B_lo[idx] = __float2bfloat16(w - __bfloat162float(hi));
    }
    for (int idx = bid * NTHR + tid; idx < 8 * 256; idx += NBLK * NTHR) {
        int hb = idx >> 8, n = idx & 255;
        int gate = n >> 6, j = n & 63;
        int srow = gate * 512 + hb * 64 + j;
        g_bias[idx] = b_ih[srow] + b_hh[srow];
    }
    grid_sync();

    const int m0 = (bid & 15) * 128;
    const int hb = bid >> 4;
    if (bid < TILES) {
        for (int i = tid; i < 256; i += NTHR) biasS[i] = g_bias[hb * 256 + i];
    }

    const int b0 = (bid * BATCH) / NBLK;
    const int b1 = ((bid + 1) * BATCH) / NBLK;
    const float bout0 = b_out[0];

    // ---- MMA thread-geometry constants ----
    const int warp_m = warp & 1;          // 0/1 -> rows 0-63 / 64-127
    const int warp_n = warp >> 1;         // 0..3 -> cols 64*warp_n
    const int l7 = lane & 7, q = lane >> 3;
    const int aRowL = warp_m * 64 + (q & 1) * 8 + l7;   // + mf*16
    const int cA    = q >> 1;
    const int bRowL = warp_n * 64 + (q >> 1) * 8 + l7;  // + bp*16
    const int cB    = q & 1;

    for (int t = 0; t <= SEQ; ++t) {
        // ================= ROW PHASE =================
        for (int b = b0 + warp; b < b1; b += 8) {
            float ycur;
            if (t == 0) {
                for (int jj = lane; jj < HID; jj += 32) {
                    float h = h0[b * HID + jj];
                    __nv_bfloat16 hi = __float2bfloat16(h);
                    g_A_hi[(size_t)b * KC + 512 + jj] = hi;
                    g_A_lo[(size_t)b * KC + 512 + jj] =
                        __float2bfloat16(h - __bfloat162float(hi));
                    g_c[(size_t)b * HID + jj] = c0[b * HID + jj];
                }
                ycur = y0[b];
            } else {
                float ysum = 0.f;
                #pragma unroll
                for (int ii = 0; ii < 4; ++ii) {
                    const int j4 = lane * 4 + ii * 128;
                    uint2 uh = __ldcg((const uint2*)(g_A_hi + (size_t)b * KC + 512 + j4));
                    uint2 ul = __ldcg((const uint2*)(g_A_lo + (size_t)b * KC + 512 + j4));
                    __nv_bfloat162 h01 = *(__nv_bfloat162*)&uh.x;
                    __nv_bfloat162 h23 = *(__nv_bfloat162*)&uh.y;
                    __nv_bfloat162 l01 = *(__nv_bfloat162*)&ul.x;
                    __nv_bfloat162 l23 = *(__nv_bfloat162*)&ul.y;
                    float2 fh01 = __bfloat1622float2(h01), fh23 = __bfloat1622float2(h23);
                    float2 fl01 = __bfloat1622float2(l01), fl23 = __bfloat1622float2(l23);
                    const float4 wv = *(const float4*)(woutS + j4);
                    ysum += (fh01.x + fl01.x) * wv.x + (fh01.y + fl01.y) * wv.y
                          + (fh23.x + fl23.x) * wv.z + (fh23.y + fl23.y) * wv.w;
                }
                #pragma unroll
                for (int off = 16; off > 0; off >>= 1)
                    ysum += __shfl_down_sync(0xffffffffu, ysum, off);
                ysum = __shfl_sync(0xffffffffu, ysum, 0);
                ycur = ysum + bout0;
                if (lane == 0) out[(size_t)(t - 1) * BATCH + b] = ycur;
            }
            if (t < SEQ) {
                if (lane < 31) inpS[warp * 32 + lane] = x[((size_t)t * BATCH + b) * 31 + lane];
                if (lane == 31) inpS[warp * 32 + 31] = ycur;
                __syncwarp();
                #pragma unroll
                for (int ii = 0; ii < 4; ++ii) {
                    const int j4 = lane * 4 + ii * 128;
                    float4 acc = *(const float4*)(binS + j4);
                    #pragma unroll
                    for (int k = 0; k < 32; ++k) {
                        const float a = inpS[warp * 32 + k];
                        const float4 w = *(const float4*)(g_WiT + k * HID + j4);
                        acc.x += a * w.x; acc.y += a * w.y;
                        acc.z += a * w.z; acc.w += a * w.w;
                    }
                    acc.x = fmaxf(acc.x, 0.f); acc.y = fmaxf(acc.y, 0.f);
                    acc.z = fmaxf(acc.z, 0.f); acc.w = fmaxf(acc.w, 0.f);
                    __nv_bfloat16 a0 = __float2bfloat16(acc.x), a1 = __float2bfloat16(acc.y);
                    __nv_bfloat16 a2 = __float2bfloat16(acc.z), a3 = __float2bfloat16(acc.w);
                    *(__nv_bfloat162*)(g_A_hi + (size_t)b * KC + j4)     = __halves2bfloat162(a0, a1);
                    *(__nv_bfloat162*)(g_A_hi + (size_t)b * KC + j4 + 2) = __halves2bfloat162(a2, a3);
                    *(__nv_bfloat162*)(g_A_lo + (size_t)b * KC + j4) = __halves2bfloat162(
                        __float2bfloat16(acc.x - __bfloat162float(a0)),
                        __float2bfloat16(acc.y - __bfloat162float(a1)));
                    *(__nv_bfloat162*)(g_A_lo + (size_t)b * KC + j4 + 2) = __halves2bfloat162(
                        __float2bfloat16(acc.z - __bfloat162float(a2)),
                        __float2bfloat16(acc.w - __bfloat162float(a3)));
                }
                __syncwarp();
            }
        }
        if (t == SEQ) break;

        grid_sync();   // A complete -> GEMM may read

        // ================= MMA PHASE (mma.sync bf16, split hi/lo) =================
        if (bid < TILES) {
            float acc[4][8][4];
            #pragma unroll
            for (int mf = 0; mf < 4; ++mf)
                #pragma unroll
                for (int nf = 0; nf < 8; ++nf)
                    #pragma unroll
                    for (int e = 0; e < 4; ++e) acc[mf][nf][e] = 0.f;

            issue_slab(sb, 0, m0, hb, tid); cp_commit();
            issue_slab(sb + STAGE, 1, m0, hb, tid); cp_commit();

            for (int kb = 0; kb < 16; ++kb) {
                if (kb < 15) cp_wait1(); else cp_wait0();
                __syncthreads();
                const uint32_t bufb = sb + (uint32_t)(kb & 1) * STAGE;
                #pragma unroll
                for (int s4 = 0; s4 < 4; ++s4) {
                    uint32_t bh[4][4], bl[4][4];
                    #pragma unroll
                    for (int bp = 0; bp < 4; ++bp) {
                        uint32_t baddr = bufb + OFF_BHI
                            + (uint32_t)((bRowL + bp * 16) * 128)
                            + (uint32_t)((((2 * s4 + cB) ^ l7)) << 4);
                        ldmx4(bh[bp], baddr);
                        ldmx4(bl[bp], baddr + (OFF_BLO - OFF_BHI));
                    }
                    #pragma unroll
                    for (int mf = 0; mf < 4; ++mf) {
                        uint32_t ah[4], al[4];
                        uint32_t aaddr = bufb + OFF_AHI
                            + (uint32_t)((aRowL + mf * 16) * 128)
                            + (uint32_t)((((2 * s4 + cA) ^ l7)) << 4);
                        ldmx4(ah, aaddr);
                        ldmx4(al, aaddr + (OFF_ALO - OFF_AHI));
                        #pragma unroll
                        for (int nf = 0; nf < 8; ++nf) {
                            const uint32_t* bhp = &bh[nf >> 1][(nf & 1) * 2];
                            const uint32_t* blp = &bl[nf >> 1][(nf & 1) * 2];
                            mma16816(acc[mf][nf], ah, bhp);
                            mma16816(acc[mf][nf], ah, blp);
                            mma16816(acc[mf][nf], al, bhp);
                        }
                    }
                }
                __syncthreads();
                if (kb + 2 < 16) { issue_slab(sb + (uint32_t)(kb & 1) * STAGE, kb + 2, m0, hb, tid); cp_commit(); }
            }

            // ---- store accums to gates smem tile (reuse stage region) ----
            float* G = (float*)base;
            #pragma unroll
            for (int mf = 0; mf < 4; ++mf) {
                const int r = warp_m * 64 + mf * 16 + (lane >> 2);
                #pragma unroll
                for (int nf = 0; nf < 8; ++nf) {
                    const int c = warp_n * 64 + nf * 8 + 2 * (lane & 3);
                    *(float2*)&G[r * GSTR + c]       = make_float2(acc[mf][nf][0], acc[mf][nf][1]);
                    *(float2*)&G[(r + 8) * GSTR + c] = make_float2(acc[mf][nf][2], acc[mf][nf][3]);
                }
            }
            __syncthreads();

            // ---- fused LSTM epilogue from gates smem ----
            const int r   = warp * 16 + (lane & 15);
            const int jb  = (lane >> 4) * 32;
            const int rg  = m0 + r;
            float* crow = g_c + (size_t)rg * HID + hb * 64;
            __nv_bfloat16* hrow_hi = g_A_hi + (size_t)rg * KC + 512 + hb * 64;
            __nv_bfloat16* hrow_lo = g_A_lo + (size_t)rg * KC + 512 + hb * 64;
            #pragma unroll
            for (int j = 0; j < 32; j += 4) {
                const int jj = jb + j;
                float4 vi = *(const float4*)&G[r * GSTR + 0   + jj];
                float4 vf = *(const float4*)&G[r * GSTR + 64  + jj];
                float4 vg = *(const float4*)&G[r * GSTR + 128 + jj];
                float4 vo = *(const float4*)&G[r * GSTR + 192 + jj];
                float4 cv = *(const float4*)(crow + jj);
                float I0 = sigf(vi.x + biasS[jj]);
                float I1 = sigf(vi.y + biasS[jj + 1]);
                float I2 = sigf(vi.z + biasS[jj + 2]);
                float I3 = sigf(vi.w + biasS[jj + 3]);
                float F0 = sigf(vf.x + biasS[64 + jj]);
                float F1 = sigf(vf.y + biasS[64 + jj + 1]);
                float F2 = sigf(vf.z + biasS[64 + jj + 2]);
                float F3 = sigf(vf.w + biasS[64 + jj + 3]);
                float G0 = tanh_(vg.x + biasS[128 + jj]);
                float G1 = tanh_(vg.y + biasS[128 + jj + 1]);
                float G2 = tanh_(vg.z + biasS[128 + jj + 2]);
                float G3 = tanh_(vg.w + biasS[128 + jj + 3]);
                float O0 = sigf(vo.x + biasS[192 + jj]);
                float O1 = sigf(vo.y + biasS[192 + jj + 1]);
                float O2 = sigf(vo.z + biasS[192 + jj + 2]);
                float O3 = sigf(vo.w + biasS[192 + jj + 3]);
                float4 cn;
                cn.x = F0 * cv.x + I0 * G0;
                cn.y = F1 * cv.y + I1 * G1;
                cn.z = F2 * cv.z + I2 * G2;
                cn.w = F3 * cv.w + I3 * G3;
                *(float4*)(crow + jj) = cn;
                float h0f = O0 * tanh_(cn.x);
                float h1f = O1 * tanh_(cn.y);
                float h2f = O2 * tanh_(cn.z);
                float h3f = O3 * tanh_(cn.w);
                __nv_bfloat16 hh0 = __float2bfloat16(h0f);
                __nv_bfloat16 hh1 = __float2bfloat16(h1f);
                __nv_bfloat16 hh2 = __float2bfloat16(h2f);
                __nv_bfloat16 hh3 = __float2bfloat16(h3f);
                *(__nv_bfloat162*)(hrow_hi + jj)     = __halves2bfloat162(hh0, hh1);
                *(__nv_bfloat162*)(hrow_hi + jj + 2) = __halves2bfloat162(hh2, hh3);
                *(__nv_bfloat162*)(hrow_lo + jj) = __halves2bfloat162(
                    __float2bfloat16(h0f - __bfloat162float(hh0)),
                    __float2bfloat16(h1f - __bfloat162float(hh1)));
                *(__nv_bfloat162*)(hrow_lo + jj + 2) = __halves2bfloat162(
                    __float2bfloat16(h2f - __bfloat162float(hh2)),
                    __float2bfloat16(h3f - __bfloat162float(hh3)));
            }
        }

        grid_sync();   // h complete -> next row phase may read
    }
}

extern "C" void kernel_launch(void* const* d_in, const int* in_sizes, int n_in,
                              void* d_out, int out_size) {
    (void)in_sizes; (void)n_in; (void)out_size;
    const float* x     = (const float*)d_in[0];
    const float* h0    = (const float*)d_in[1];
    const float* c0    = (const float*)d_in[2];
    const float* y0    = (const float*)d_in[3];
    const float* W_in  = (const float*)d_in[4];
    const float* b_in  = (const float*)d_in[5];
    const float* W_ih  = (const float*)d_in[6];
    const float* W_hh  = (const float*)d_in[7];
    const float* b_ih  = (const float*)d_in[8];
    const float* b_hh  = (const float*)d_in[9];
    const float* W_out = (const float*)d_in[10];
    const float* b_out = (const float*)d_in[11];
    float* out = (float*)d_out;

    cudaFuncSetAttribute(lstm_persist, cudaFuncAttributeMaxDynamicSharedMemorySize, DYNSMEM);
    lstm_persist<<<NBLK, NTHR, DYNSMEM>>>(x, h0, c0, y0, W_in, b_in, W_ih, W_hh,
                                          b_ih, b_hh, W_out, b_out, out);
}

// round 7
// speedup vs baseline: 3.0114x; 1.0196x over previous
#include <cuda_runtime.h>
#include <cuda_bf16.h>
#include <math.h>
#include <stdint.h>

#define SEQ   512
#define BATCH 2048
#define HID   512
#define KC    1024
#define NBLK  148
#define NTHR  256
#define TILES 128           // 16 m-tiles x 8 h-tiles
#define STAGE 98304
#define OFF_AHI 0
#define OFF_ALO 16384
#define OFF_BHI 32768
#define OFF_BLO 65536
#define DYNSMEM (2*STAGE + 1024)
#define GSTR  264           // gates smem row stride (floats)
#define NRMAX 14

// ---------------- persistent device state (no allocs) ----------------
__device__ __align__(16) __nv_bfloat16 g_A_hi[BATCH * KC];   // [b][k] k<512:x0, k>=512:h
__device__ __align__(16) __nv_bfloat16 g_A_lo[BATCH * KC];
__device__ __align__(16) __nv_bfloat16 g_B_hi[8 * 256 * KC]; // [hb][n'][k], n'=gate*64+j
__device__ __align__(16) __nv_bfloat16 g_B_lo[8 * 256 * KC];
__device__ float g_bias[8 * 256];
__device__ float g_c[BATCH * HID];
__device__ float g_WiT[32 * HID];
__device__ float g_ypart[BATCH * 8];   // [b][hb] partial y dot products
__device__ unsigned g_bar_count;
__device__ volatile unsigned g_bar_gen;

// ---------------- helpers ----------------
__device__ __forceinline__ uint32_t smaddr(const void* p) {
    return (uint32_t)__cvta_generic_to_shared(p);
}
__device__ __forceinline__ void cpasync16(uint32_t dst, const void* src) {
    asm volatile("cp.async.cg.shared.global [%0], [%1], 16;" :: "r"(dst), "l"(src));
}
__device__ __forceinline__ void cp_commit() {
    asm volatile("cp.async.commit_group;" ::: "memory");
}
__device__ __forceinline__ void cp_wait1() {
    asm volatile("cp.async.wait_group 1;" ::: "memory");
}
__device__ __forceinline__ void cp_wait0() {
    asm volatile("cp.async.wait_group 0;" ::: "memory");
}
__device__ __forceinline__ void ldmx4(uint32_t* r, uint32_t addr) {
    asm volatile("ldmatrix.sync.aligned.m8n8.x4.shared.b16 {%0,%1,%2,%3}, [%4];"
                 : "=r"(r[0]), "=r"(r[1]), "=r"(r[2]), "=r"(r[3]) : "r"(addr));
}
__device__ __forceinline__ void mma16816(float* d, const uint32_t* a, const uint32_t* b) {
    asm volatile("mma.sync.aligned.m16n8k16.row.col.f32.bf16.bf16.f32 "
                 "{%0,%1,%2,%3}, {%4,%5,%6,%7}, {%8,%9}, {%0,%1,%2,%3};"
                 : "+f"(d[0]), "+f"(d[1]), "+f"(d[2]), "+f"(d[3])
                 : "r"(a[0]), "r"(a[1]), "r"(a[2]), "r"(a[3]), "r"(b[0]), "r"(b[1]));
}

__device__ __forceinline__ void grid_sync() {
    __syncthreads();
    if (threadIdx.x == 0) {
        unsigned gen = g_bar_gen;
        __threadfence();
        if (atomicAdd(&g_bar_count, 1u) == (unsigned)(NBLK - 1)) {
            g_bar_count = 0;
            __threadfence();
            g_bar_gen = gen + 1;
        } else {
            while (g_bar_gen == gen) { __nanosleep(64); }
        }
        __threadfence();
    }
    __syncthreads();
}

__device__ __forceinline__ float sigf(float v) {
    return __fdividef(1.0f, 1.0f + __expf(-v));
}
__device__ __forceinline__ float tanh_(float v) {
    return 2.0f * sigf(2.0f * v) - 1.0f;
}

// issue one k-slab (64 k) of A(hi/lo) + B(hi/lo) via cp.async into stage buffer
__device__ __forceinline__ void issue_slab(uint32_t dstbase, int kb, int m0, int hb, int tid) {
    #pragma unroll
    for (int i = 0; i < 4; ++i) {
        int c = tid + i * 256;
        int row = c >> 3, kq = c & 7;
        size_t so = ((size_t)(m0 + row) * KC + (size_t)kb * 64 + kq * 8) * 2;
        unsigned off = (unsigned)(row * 128) + (unsigned)((kq ^ (row & 7)) << 4);
        cpasync16(dstbase + OFF_AHI + off, (const char*)g_A_hi + so);
        cpasync16(dstbase + OFF_ALO + off, (const char*)g_A_lo + so);
    }
    #pragma unroll
    for (int i = 0; i < 8; ++i) {
        int c = tid + i * 256;
        int n = c >> 3, kq = c & 7;
        size_t so = (((size_t)hb * 256 + n) * KC + (size_t)kb * 64 + kq * 8) * 2;
        unsigned off = (unsigned)(n * 128) + (unsigned)((kq ^ (n & 7)) << 4);
        cpasync16(dstbase + OFF_BHI + off, (const char*)g_B_hi + so);
        cpasync16(dstbase + OFF_BLO + off, (const char*)g_B_lo + so);
    }
}

__global__ __launch_bounds__(NTHR, 1) void lstm_persist(
    const float* __restrict__ x,   const float* __restrict__ h0,
    const float* __restrict__ c0,  const float* __restrict__ y0,
    const float* __restrict__ W_in,  const float* __restrict__ b_in,
    const float* __restrict__ W_ih,  const float* __restrict__ W_hh,
    const float* __restrict__ b_ih,  const float* __restrict__ b_hh,
    const float* __restrict__ W_out, const float* __restrict__ b_out,
    float* __restrict__ out)
{
    extern __shared__ char dsm[];
    __shared__ float binS [HID];
    __shared__ float woutS[HID];
    __shared__ float biasS[256];
    __shared__ float inpS [NRMAX * 32];

    const int tid  = threadIdx.x;
    const int bid  = blockIdx.x;
    const int warp = tid >> 5, lane = tid & 31;

    // align dynamic smem to 1KB
    uint32_t raw = smaddr(dsm);
    uint32_t sb  = (raw + 1023u) & ~1023u;
    char* base   = dsm + (sb - raw);

    // ---- small per-CTA staging ----
    for (int i = tid; i < HID; i += NTHR) { binS[i] = b_in[i]; woutS[i] = W_out[i]; }

    // ---- one-time global init (striped across grid) ----
    for (int idx = bid * NTHR + tid; idx < 32 * HID; idx += NBLK * NTHR) {
        int j = idx >> 5, k = idx & 31;
        g_WiT[k * HID + j] = W_in[j * 32 + k];
    }
    for (int idx = bid * NTHR + tid; idx < 8 * 256 * KC; idx += NBLK * NTHR) {
        int hb = idx >> 18, rem = idx & 0x3FFFF;
        int n = rem >> 10, k = rem & 1023;
        int gate = n >> 6, j = n & 63;
        int srow = gate * 512 + hb * 64 + j;
        float w = (k < 512) ? W_ih[srow * 512 + k] : W_hh[srow * 512 + (k - 512)];
        __nv_bfloat16 hi = __float2bfloat16(w);
        g_B_hi[idx] = hi;
        g_B_lo[idx] = __float2bfloat16(w - __bfloat162float(hi));
    }
    for (int idx = bid * NTHR + tid; idx < 8 * 256; idx += NBLK * NTHR) {
        int hb = idx >> 8, n = idx & 255;
        int gate = n >> 6, j = n & 63;
        int srow = gate * 512 + hb * 64 + j;
        g_bias[idx] = b_ih[srow] + b_hh[srow];
    }
    grid_sync();

    const int m0 = (bid & 15) * 128;
    const int hb = bid >> 4;
    if (bid < TILES) {
        for (int i = tid; i < 256; i += NTHR) biasS[i] = g_bias[hb * 256 + i];
    }

    const int b0 = (bid * BATCH) / NBLK;
    const int b1 = ((bid + 1) * BATCH) / NBLK;
    const int NR = b1 - b0;
    const float bout0 = b_out[0];

    // ---- MMA thread-geometry constants ----
    const int warp_m = warp & 1;          // 0/1 -> rows 0-63 / 64-127
    const int warp_n = warp >> 1;         // 0..3 -> cols 64*warp_n
    const int l7 = lane & 7, q = lane >> 3;
    const int aRowL = warp_m * 64 + (q & 1) * 8 + l7;   // + mf*16
    const int cA    = q >> 1;
    const int bRowL = warp_n * 64 + (q >> 1) * 8 + l7;  // + bp*16
    const int cB    = q & 1;

    for (int t = 0; t <= SEQ; ++t) {
        // ================= ROW PHASE =================
        if (t == 0) {
            // init h (bf16 split), c
            for (int b = b0 + warp; b < b1; b += 8) {
                for (int jj = lane; jj < HID; jj += 32) {
                    float h = h0[b * HID + jj];
                    __nv_bfloat16 hi = __float2bfloat16(h);
                    g_A_hi[(size_t)b * KC + 512 + jj] = hi;
                    g_A_lo[(size_t)b * KC + 512 + jj] =
                        __float2bfloat16(h - __bfloat162float(hi));
                    g_c[(size_t)b * HID + jj] = c0[b * HID + jj];
                }
            }
        }
        // ---- y per row (sum of 8 epilogue partials), write out ----
        if (tid < NR) {
            const int b = b0 + tid;
            float yv;
            if (t == 0) {
                yv = y0[b];
            } else {
                float s = bout0;
                #pragma unroll
                for (int p = 0; p < 8; ++p)
                    s += __ldcg(&g_ypart[(size_t)b * 8 + p]);
                out[(size_t)(t - 1) * BATCH + b] = s;
                yv = s;
            }
            if (t < SEQ) inpS[tid * 32 + 31] = yv;
        }
        if (t == SEQ) break;

        // ---- stage x into inpS ----
        for (int i = tid; i < NR * 31; i += NTHR) {
            int r = i / 31, cc = i - r * 31;
            inpS[r * 32 + cc] = __ldcg(&x[((size_t)t * BATCH + (b0 + r)) * 31 + cc]);
        }
        __syncthreads();

        // ---- col-block x0 GEMM: warp owns 64 cols, lane owns 2, all NR rows ----
        {
            const int jc = warp * 64 + lane * 2;
            const float2 bb = *(const float2*)(binS + jc);
            float2 ac[NRMAX];
            #pragma unroll
            for (int r = 0; r < NRMAX; ++r) ac[r] = bb;
            #pragma unroll 4
            for (int k = 0; k < 32; ++k) {
                const float2 w = *(const float2*)(g_WiT + k * HID + jc);
                #pragma unroll
                for (int r = 0; r < NRMAX; ++r) {
                    if (r < NR) {
                        const float a = inpS[r * 32 + k];
                        ac[r].x = fmaf(a, w.x, ac[r].x);
                        ac[r].y = fmaf(a, w.y, ac[r].y);
                    }
                }
            }
            #pragma unroll
            for (int r = 0; r < NRMAX; ++r) {
                if (r < NR) {
                    float vx = fmaxf(ac[r].x, 0.f), vy = fmaxf(ac[r].y, 0.f);
                    __nv_bfloat16 hx = __float2bfloat16(vx);
                    __nv_bfloat16 hy = __float2bfloat16(vy);
                    *(__nv_bfloat162*)(g_A_hi + (size_t)(b0 + r) * KC + jc) =
                        __halves2bfloat162(hx, hy);
                    *(__nv_bfloat162*)(g_A_lo + (size_t)(b0 + r) * KC + jc) =
                        __halves2bfloat162(
                            __float2bfloat16(vx - __bfloat162float(hx)),
                            __float2bfloat16(vy - __bfloat162float(hy)));
                }
            }
        }

        grid_sync();   // A complete -> GEMM may read

        // ================= MMA PHASE (mma.sync bf16, split hi/lo) =================
        if (bid < TILES) {
            float acc[4][8][4];
            #pragma unroll
            for (int mf = 0; mf < 4; ++mf)
                #pragma unroll
                for (int nf = 0; nf < 8; ++nf)
                    #pragma unroll
                    for (int e = 0; e < 4; ++e) acc[mf][nf][e] = 0.f;

            issue_slab(sb, 0, m0, hb, tid); cp_commit();
            issue_slab(sb + STAGE, 1, m0, hb, tid); cp_commit();

            for (int kb = 0; kb < 16; ++kb) {
                if (kb < 15) cp_wait1(); else cp_wait0();
                __syncthreads();
                const uint32_t bufb = sb + (uint32_t)(kb & 1) * STAGE;
                #pragma unroll
                for (int s4 = 0; s4 < 4; ++s4) {
                    uint32_t bh[4][4], bl[4][4];
                    #pragma unroll
                    for (int bp = 0; bp < 4; ++bp) {
                        uint32_t baddr = bufb + OFF_BHI
                            + (uint32_t)((bRowL + bp * 16) * 128)
                            + (uint32_t)((((2 * s4 + cB) ^ l7)) << 4);
                        ldmx4(bh[bp], baddr);
                        ldmx4(bl[bp], baddr + (OFF_BLO - OFF_BHI));
                    }
                    // term-major ordering: 8 independent MMAs between reuses of
                    // any accumulator (same per-acc FP order as before: hh, hl, lh)
                    #pragma unroll
                    for (int mf = 0; mf < 4; ++mf) {
                        uint32_t ah[4], al[4];
                        uint32_t aaddr = bufb + OFF_AHI
                            + (uint32_t)((aRowL + mf * 16) * 128)
                            + (uint32_t)((((2 * s4 + cA) ^ l7)) << 4);
                        ldmx4(ah, aaddr);
                        ldmx4(al, aaddr + (OFF_ALO - OFF_AHI));
                        #pragma unroll
                        for (int nf = 0; nf < 8; ++nf)
                            mma16816(acc[mf][nf], ah, &bh[nf >> 1][(nf & 1) * 2]);
                        #pragma unroll
                        for (int nf = 0; nf < 8; ++nf)
                            mma16816(acc[mf][nf], ah, &bl[nf >> 1][(nf & 1) * 2]);
                        #pragma unroll
                        for (int nf = 0; nf < 8; ++nf)
                            mma16816(acc[mf][nf], al, &bh[nf >> 1][(nf & 1) * 2]);
                    }
                }
                __syncthreads();
                if (kb + 2 < 16) { issue_slab(sb + (uint32_t)(kb & 1) * STAGE, kb + 2, m0, hb, tid); cp_commit(); }
            }

            // ---- store accums to gates smem tile (reuse stage region) ----
            float* G = (float*)base;
            #pragma unroll
            for (int mf = 0; mf < 4; ++mf) {
                const int r = warp_m * 64 + mf * 16 + (lane >> 2);
                #pragma unroll
                for (int nf = 0; nf < 8; ++nf) {
                    const int c = warp_n * 64 + nf * 8 + 2 * (lane & 3);
                    *(float2*)&G[r * GSTR + c]       = make_float2(acc[mf][nf][0], acc[mf][nf][1]);
                    *(float2*)&G[(r + 8) * GSTR + c] = make_float2(acc[mf][nf][2], acc[mf][nf][3]);
                }
            }
            __syncthreads();

            // ---- fused LSTM epilogue from gates smem + partial-y ----
            const int r   = warp * 16 + (lane & 15);
            const int jb  = (lane >> 4) * 32;
            const int rg  = m0 + r;
            float* crow = g_c + (size_t)rg * HID + hb * 64;
            __nv_bfloat16* hrow_hi = g_A_hi + (size_t)rg * KC + 512 + hb * 64;
            __nv_bfloat16* hrow_lo = g_A_lo + (size_t)rg * KC + 512 + hb * 64;
            float ypart = 0.f;
            #pragma unroll
            for (int j = 0; j < 32; j += 4) {
                const int jj = jb + j;
                float4 vi = *(const float4*)&G[r * GSTR + 0   + jj];
                float4 vf = *(const float4*)&G[r * GSTR + 64  + jj];
                float4 vg = *(const float4*)&G[r * GSTR + 128 + jj];
                float4 vo = *(const float4*)&G[r * GSTR + 192 + jj];
                float4 cv = *(const float4*)(crow + jj);
                float I0 = sigf(vi.x + biasS[jj]);
                float I1 = sigf(vi.y + biasS[jj + 1]);
                float I2 = sigf(vi.z + biasS[jj + 2]);
                float I3 = sigf(vi.w + biasS[jj + 3]);
                float F0 = sigf(vf.x + biasS[64 + jj]);
                float F1 = sigf(vf.y + biasS[64 + jj + 1]);
                float F2 = sigf(vf.z + biasS[64 + jj + 2]);
                float F3 = sigf(vf.w + biasS[64 + jj + 3]);
                float G0 = tanh_(vg.x + biasS[128 + jj]);
                float G1 = tanh_(vg.y + biasS[128 + jj + 1]);
                float G2 = tanh_(vg.z + biasS[128 + jj + 2]);
                float G3 = tanh_(vg.w + biasS[128 + jj + 3]);
                float O0 = sigf(vo.x + biasS[192 + jj]);
                float O1 = sigf(vo.y + biasS[192 + jj + 1]);
                float O2 = sigf(vo.z + biasS[192 + jj + 2]);
                float O3 = sigf(vo.w + biasS[192 + jj + 3]);
                float4 cn;
                cn.x = F0 * cv.x + I0 * G0;
                cn.y = F1 * cv.y + I1 * G1;
                cn.z = F2 * cv.z + I2 * G2;
                cn.w = F3 * cv.w + I3 * G3;
                *(float4*)(crow + jj) = cn;
                float h0f = O0 * tanh_(cn.x);
                float h1f = O1 * tanh_(cn.y);
                float h2f = O2 * tanh_(cn.z);
                float h3f = O3 * tanh_(cn.w);
                const float4 wv = *(const float4*)(woutS + hb * 64 + jj);
                ypart += h0f * wv.x + h1f * wv.y + h2f * wv.z + h3f * wv.w;
                __nv_bfloat16 hh0 = __float2bfloat16(h0f);
                __nv_bfloat16 hh1 = __float2bfloat16(h1f);
                __nv_bfloat16 hh2 = __float2bfloat16(h2f);
                __nv_bfloat16 hh3 = __float2bfloat16(h3f);
                *(__nv_bfloat162*)(hrow_hi + jj)     = __halves2bfloat162(hh0, hh1);
                *(__nv_bfloat162*)(hrow_hi + jj + 2) = __halves2bfloat162(hh2, hh3);
                *(__nv_bfloat162*)(hrow_lo + jj) = __halves2bfloat162(
                    __float2bfloat16(h0f - __bfloat162float(hh0)),
                    __float2bfloat16(h1f - __bfloat162float(hh1)));
                *(__nv_bfloat162*)(hrow_lo + jj + 2) = __halves2bfloat162(
                    __float2bfloat16(h2f - __bfloat162float(hh2)),
                    __float2bfloat16(h3f - __bfloat162float(hh3)));
            }
            // combine the two half-row partials (lanes l and l^16 share a row)
            ypart += __shfl_xor_sync(0xffffffffu, ypart, 16);
            if (lane < 16) g_ypart[(size_t)rg * 8 + hb] = ypart;
        }

        grid_sync();   // h + ypart complete -> next row phase may read
    }
}

extern "C" void kernel_launch(void* const* d_in, const int* in_sizes, int n_in,
                              void* d_out, int out_size) {
    (void)in_sizes; (void)n_in; (void)out_size;
    const float* x     = (const float*)d_in[0];
    const float* h0    = (const float*)d_in[1];
    const float* c0    = (const float*)d_in[2];
    const float* y0    = (const float*)d_in[3];
    const float* W_in  = (const float*)d_in[4];
    const float* b_in  = (const float*)d_in[5];
    const float* W_ih  = (const float*)d_in[6];
    const float* W_hh  = (const float*)d_in[7];
    const float* b_ih  = (const float*)d_in[8];
    const float* b_hh  = (const float*)d_in[9];
    const float* W_out = (const float*)d_in[10];
    const float* b_out = (const float*)d_in[11];
    float* out = (float*)d_out;

    cudaFuncSetAttribute(lstm_persist, cudaFuncAttributeMaxDynamicSharedMemorySize, DYNSMEM);
    lstm_persist<<<NBLK, NTHR, DYNSMEM>>>(x, h0, c0, y0, W_in, b_in, W_ih, W_hh,
                                          b_ih, b_hh, W_out, b_out, out);
}